// round 1
// baseline (speedup 1.0000x reference)
#include <cuda_runtime.h>

#define B_    256
#define T_    512
#define IN_   64
#define H_    1024
#define OUT_  128
#define NBLK  128

// ---------------- persistent scratch (no allocs allowed) ----------------
__device__ float g_WhT[H_ * H_];        // WhT[k][n] = Wh[n][k]        (4 MB)
__device__ float g_WxT[IN_ * H_];       // WxT[i][n] = Wx[n][i]        (256 KB)
__device__ float g_WoT[H_ * OUT_];      // WoT[k][o] = Wo[o][k]        (512 KB)
__device__ float g_xT[T_ * IN_ * B_];   // xT[t][i][m] = x[m][t][i]    (128 MB)
__device__ float g_h0[H_ * B_];         // hT[n][m] ping                (1 MB)
__device__ float g_h1[H_ * B_];         // hT[n][m] pong                (1 MB)

__device__ unsigned g_bar_count;
__device__ volatile unsigned g_bar_gen;

// ---------------- software grid barrier (all 128 CTAs resident) --------
__device__ __forceinline__ void grid_sync() {
    __syncthreads();
    if (threadIdx.x == 0) {
        __threadfence();
        unsigned gen = g_bar_gen;
        if (atomicAdd(&g_bar_count, 1u) == NBLK - 1u) {
            atomicExch(&g_bar_count, 0u);
            __threadfence();
            g_bar_gen = gen + 1u;
        } else {
            while (g_bar_gen == gen) { __nanosleep(32); }
        }
        __threadfence();
    }
    __syncthreads();
}

// ---------------- generic 32x32 tiled transpose -------------------------
// out[c][r] = in[r][c], R and C multiples of 32.
__global__ void transpose32(const float* __restrict__ in, float* __restrict__ out,
                            int R, int C) {
    __shared__ float tile[32][33];
    const int c0 = blockIdx.x * 32;
    const int r0 = blockIdx.y * 32;
#pragma unroll
    for (int i = threadIdx.y; i < 32; i += 8)
        tile[i][threadIdx.x] = in[(size_t)(r0 + i) * C + (c0 + threadIdx.x)];
    __syncthreads();
#pragma unroll
    for (int i = threadIdx.y; i < 32; i += 8)
        out[(size_t)(c0 + i) * R + (r0 + threadIdx.x)] = tile[threadIdx.x][i];
}

// ---------------- persistent RNN kernel ---------------------------------
// 128 CTAs x 128 threads. CTA tile: 32 (batch rows) x 64 (hidden cols).
// Thread tile 4x4. K = 1088 fused (Wh: 1024 + Wx: 64), chunks of 32.
// SMEM layout [k][row] -> coalesced stores, aligned float4 reads.
__global__ void __launch_bounds__(128, 1) rnn_persistent(float* __restrict__ out) {
    const int tid = threadIdx.x;
    const int bid = blockIdx.x;
    const int m0 = (bid >> 4) << 5;   // batch-row tile (8 tiles of 32)
    const int n0 = (bid & 15) << 6;   // hidden-col tile (16 tiles of 64)

    __shared__ __align__(16) float As[32 * 32];   // As[kl][ml]
    __shared__ __align__(16) float Bs[32 * 64];   // Bs[kl][nl]

    // h_{-1} = 0
    for (int i = bid * 128 + tid; i < H_ * B_; i += NBLK * 128) g_h0[i] = 0.f;
    grid_sync();

    // per-thread load/compute offsets
    const int aoff = (tid >> 3) * B_ + m0 + (tid & 7) * 4;     // A gmem
    const int sa   = (tid >> 3) * 32 + (tid & 7) * 4;          // A smem
    const int boff = (tid >> 4) * H_ + n0 + (tid & 15) * 4;    // B gmem
    const int sb   = (tid >> 4) * 64 + (tid & 15) * 4;         // B smem
    const int r4   = (tid >> 4) * 4;                           // my 4 rows
    const int c4   = (tid & 15) * 4;                           // my 4 cols

    for (int t = 0; t < T_; ++t) {
        const float* __restrict__ hc = (t & 1) ? g_h1 : g_h0;
        float* __restrict__ hn       = (t & 1) ? g_h0 : g_h1;

        float acc[4][4];
#pragma unroll
        for (int i = 0; i < 4; ++i)
#pragma unroll
            for (int j = 0; j < 4; ++j) acc[i][j] = 0.f;

        // prologue: prefetch chunk 0 (k0 = 0: hT + WhT)
        float4 ra0 = *(const float4*)(hc + aoff);
        float4 ra1 = *(const float4*)(hc + aoff + 16 * B_);
        float4 rb0 = *(const float4*)(g_WhT + boff);
        float4 rb1 = *(const float4*)(g_WhT + boff + 8 * H_);
        float4 rb2 = *(const float4*)(g_WhT + boff + 16 * H_);
        float4 rb3 = *(const float4*)(g_WhT + boff + 24 * H_);

        for (int ch = 0; ch < 34; ++ch) {
            __syncthreads();
            *(float4*)(As + sa)            = ra0;
            *(float4*)(As + sa + 16 * 32)  = ra1;
            *(float4*)(Bs + sb)            = rb0;
            *(float4*)(Bs + sb + 8 * 64)   = rb1;
            *(float4*)(Bs + sb + 16 * 64)  = rb2;
            *(float4*)(Bs + sb + 24 * 64)  = rb3;
            __syncthreads();

            if (ch + 1 < 34) {   // prefetch next chunk (overlaps compute)
                const int k0 = (ch + 1) * 32;
                const float* __restrict__ Ap;
                const float* __restrict__ Bp;
                if (k0 < H_) { Ap = hc + k0 * B_;                        Bp = g_WhT + k0 * H_; }
                else         { Ap = g_xT + t * (IN_ * B_) + (k0 - H_) * B_; Bp = g_WxT + (k0 - H_) * H_; }
                ra0 = *(const float4*)(Ap + aoff);
                ra1 = *(const float4*)(Ap + aoff + 16 * B_);
                rb0 = *(const float4*)(Bp + boff);
                rb1 = *(const float4*)(Bp + boff + 8 * H_);
                rb2 = *(const float4*)(Bp + boff + 16 * H_);
                rb3 = *(const float4*)(Bp + boff + 24 * H_);
            }

#pragma unroll
            for (int kk = 0; kk < 32; ++kk) {
                float4 a = *(const float4*)(As + kk * 32 + r4);
                float4 b = *(const float4*)(Bs + kk * 64 + c4);
                acc[0][0] = fmaf(a.x, b.x, acc[0][0]);
                acc[0][1] = fmaf(a.x, b.y, acc[0][1]);
                acc[0][2] = fmaf(a.x, b.z, acc[0][2]);
                acc[0][3] = fmaf(a.x, b.w, acc[0][3]);
                acc[1][0] = fmaf(a.y, b.x, acc[1][0]);
                acc[1][1] = fmaf(a.y, b.y, acc[1][1]);
                acc[1][2] = fmaf(a.y, b.z, acc[1][2]);
                acc[1][3] = fmaf(a.y, b.w, acc[1][3]);
                acc[2][0] = fmaf(a.z, b.x, acc[2][0]);
                acc[2][1] = fmaf(a.z, b.y, acc[2][1]);
                acc[2][2] = fmaf(a.z, b.z, acc[2][2]);
                acc[2][3] = fmaf(a.z, b.w, acc[2][3]);
                acc[3][0] = fmaf(a.w, b.x, acc[3][0]);
                acc[3][1] = fmaf(a.w, b.y, acc[3][1]);
                acc[3][2] = fmaf(a.w, b.z, acc[3][2]);
                acc[3][3] = fmaf(a.w, b.w, acc[3][3]);
            }
        }

        // relu + store hT[n][m] (transposed so next step's A loads stay coalesced)
#pragma unroll
        for (int j = 0; j < 4; ++j) {
            float4 v;
            v.x = fmaxf(acc[0][j], 0.f);
            v.y = fmaxf(acc[1][j], 0.f);
            v.z = fmaxf(acc[2][j], 0.f);
            v.w = fmaxf(acc[3][j], 0.f);
            *(float4*)(hn + (n0 + c4 + j) * B_ + m0 + r4) = v;
        }
        grid_sync();
    }

    // final: out[m][o] = sum_k hT[k][m] * WoT[k][o]   (final h is in g_h0)
    const float* __restrict__ hf = g_h0;
    const int m = bid * 2;
    float s0 = 0.f, s1 = 0.f;
#pragma unroll 8
    for (int k = 0; k < H_; ++k) {
        float w = g_WoT[k * OUT_ + tid];
        s0 = fmaf(hf[k * B_ + m], w, s0);
        s1 = fmaf(hf[k * B_ + m + 1], w, s1);
    }
    out[m * OUT_ + tid]       = s0;
    out[(m + 1) * OUT_ + tid] = s1;
}

// ---------------- launch ------------------------------------------------
extern "C" void kernel_launch(void* const* d_in, const int* in_sizes, int n_in,
                              void* d_out, int out_size) {
    (void)in_sizes; (void)n_in; (void)out_size;
    const float* x  = (const float*)d_in[0];
    const float* Wh = (const float*)d_in[1];
    const float* Wx = (const float*)d_in[2];
    const float* Wo = (const float*)d_in[3];
    float* out = (float*)d_out;

    float *pWhT, *pWxT, *pWoT, *pxT;
    cudaGetSymbolAddress((void**)&pWhT, g_WhT);
    cudaGetSymbolAddress((void**)&pWxT, g_WxT);
    cudaGetSymbolAddress((void**)&pWoT, g_WoT);
    cudaGetSymbolAddress((void**)&pxT,  g_xT);

    dim3 tb(32, 8);
    // WhT[k][n] from Wh[n][k] : R=H, C=H
    transpose32<<<dim3(H_ / 32, H_ / 32), tb>>>(Wh, pWhT, H_, H_);
    // WxT[i][n] from Wx[n][i] : R=H, C=IN
    transpose32<<<dim3(IN_ / 32, H_ / 32), tb>>>(Wx, pWxT, H_, IN_);
    // WoT[k][o] from Wo[o][k] : R=OUT, C=H
    transpose32<<<dim3(H_ / 32, OUT_ / 32), tb>>>(Wo, pWoT, OUT_, H_);
    // xT[(t,i)][m] from x[m][(t,i)] : R=B, C=T*IN
    transpose32<<<dim3((T_ * IN_) / 32, B_ / 32), tb>>>(x, pxT, B_, T_ * IN_);

    rnn_persistent<<<NBLK, 128>>>(out);
}

// round 3
// speedup vs baseline: 1.1659x; 1.1659x over previous
#include <cuda_runtime.h>
#include <cuda_bf16.h>
#include <cstdint>

#define B_    256
#define T_    512
#define IN_   64
#define H_    1024
#define OUT_  128
#define NCTA  128
#define NKC   68                      // K chunks of 16: 64 (h) + 4 (x_t)
#define HBUF  (16 * 64 * 2 * 32)      // uint4s per h buffer: [mt][kc][hl][lane]
#define SMEM_BYTES (NKC * 4 * 2 * 256)   // 139264 B: B slice, frag-packed

// ---------------- persistent device scratch ------------------------------
__device__ uint4 g_hA[2 * HBUF];                   // ping-pong h, A-frag packed (2 MB)
__device__ uint4 g_xp[(size_t)T_ * 16 * 4 * 2 * 32]; // x, A-frag packed per t (32 MB)
__device__ float g_hf[B_ * H_];                    // final h, plain fp32
__device__ unsigned g_bar_count;
__device__ volatile unsigned g_bar_gen;

// ---------------- helpers -------------------------------------------------
__device__ __forceinline__ uint32_t smem_u32(const void* p) {
    uint32_t a;
    asm("{ .reg .u64 t; cvta.to.shared.u64 t, %1; cvt.u32.u64 %0, t; }"
        : "=r"(a) : "l"(p));
    return a;
}

__device__ __forceinline__ uint32_t pk(float a, float b) {
    __nv_bfloat162 t = __floats2bfloat162_rn(a, b);
    return *reinterpret_cast<uint32_t*>(&t);
}

__device__ __forceinline__ void lds64(uint32_t* r, uint32_t a) {
    asm("ld.shared.v2.b32 {%0,%1}, [%2];" : "=r"(r[0]), "=r"(r[1]) : "r"(a));
}

__device__ __forceinline__ void mma16816(float* c, const uint32_t* a, const uint32_t* b) {
    asm("mma.sync.aligned.m16n8k16.row.col.f32.bf16.bf16.f32 "
        "{%0,%1,%2,%3}, {%4,%5,%6,%7}, {%8,%9}, {%0,%1,%2,%3};"
        : "+f"(c[0]), "+f"(c[1]), "+f"(c[2]), "+f"(c[3])
        : "r"(a[0]), "r"(a[1]), "r"(a[2]), "r"(a[3]), "r"(b[0]), "r"(b[1]));
}

__device__ __forceinline__ void grid_sync() {
    __syncthreads();
    if (threadIdx.x == 0) {
        __threadfence();
        unsigned gen = g_bar_gen;
        if (atomicAdd(&g_bar_count, 1u) == NCTA - 1u) {
            atomicExch(&g_bar_count, 0u);
            __threadfence();
            g_bar_gen = gen + 1u;
        } else {
            while (g_bar_gen == gen) { }
        }
        __threadfence();
    }
    __syncthreads();
}

// ---------------- pack x into A-fragment layout (one-time) ----------------
// g_xp[((t*16+mt)*4+kcx)*2 + hl][lane] : lane's uint4 = {a0,a1,a2,a3}
__global__ void pack_x(const float* __restrict__ x, uint4* __restrict__ xp) {
    int id = blockIdx.x * (blockDim.x >> 5) + (threadIdx.x >> 5);
    int l  = threadIdx.x & 31;
    if (id >= T_ * 16 * 4) return;
    int t = id >> 6, mt = (id >> 2) & 15, kcx = id & 3;
    int b0 = mt * 16 + (l >> 2), b1 = b0 + 8;
    int i0 = kcx * 16 + 2 * (l & 3);
    const float* x0 = x + ((size_t)b0 * T_ + t) * IN_;
    const float* x1 = x + ((size_t)b1 * T_ + t) * IN_;
    float v00 = x0[i0], v01 = x0[i0 + 1], v02 = x0[i0 + 8], v03 = x0[i0 + 9];
    float v10 = x1[i0], v11 = x1[i0 + 1], v12 = x1[i0 + 8], v13 = x1[i0 + 9];
    uint4 hi4, lo4;
    hi4.x = pk(v00, v01); hi4.y = pk(v10, v11);
    hi4.z = pk(v02, v03); hi4.w = pk(v12, v13);
    float r00 = v00 - __bfloat162float(__float2bfloat16(v00));
    float r01 = v01 - __bfloat162float(__float2bfloat16(v01));
    float r02 = v02 - __bfloat162float(__float2bfloat16(v02));
    float r03 = v03 - __bfloat162float(__float2bfloat16(v03));
    float r10 = v10 - __bfloat162float(__float2bfloat16(v10));
    float r11 = v11 - __bfloat162float(__float2bfloat16(v11));
    float r12 = v12 - __bfloat162float(__float2bfloat16(v12));
    float r13 = v13 - __bfloat162float(__float2bfloat16(v13));
    lo4.x = pk(r00, r01); lo4.y = pk(r10, r11);
    lo4.z = pk(r02, r03); lo4.w = pk(r12, r13);
    size_t base = (size_t)id * 64 + l;
    xp[base] = hi4;
    xp[base + 32] = lo4;
}

// ---------------- persistent mma.sync RNN --------------------------------
// 128 CTAs x 128 threads (4 warps, 2x2). CTA tile M64 x N32; warp tile 32x16.
__global__ void __launch_bounds__(128, 1) rnn_mma(
    float* __restrict__ out, const float* __restrict__ Wh,
    const float* __restrict__ Wx, const float* __restrict__ Wo,
    const uint4* __restrict__ xp, uint4* __restrict__ hA,
    float* __restrict__ hf)
{
    extern __shared__ __align__(16) uint8_t smem[];
    const int tid = threadIdx.x, l = tid & 31;
    const int wid = tid >> 5, wm = wid >> 1, wn = wid & 1;
    const int bid = blockIdx.x;
    const int m0 = (bid >> 5) << 6;        // batch tile: 4 x 64
    const int n0 = (bid & 31) << 5;        // hidden tile: 32 x 32
    const uint32_t sB = smem_u32(smem);

    // ---- one-time: pack B slice (rows n0..n0+31 of [Wh | Wx]) into smem ----
    // B-frag layout per (kc, frag, hl): 256B block, lane l holds 8B {b0,b1}
    for (int e = tid; e < 32 * 1088; e += 128) {
        int nl = e / 1088, k = e - nl * 1088;
        float v = (k < 1024) ? Wh[(size_t)(n0 + nl) * 1024 + k]
                             : Wx[(size_t)(n0 + nl) * 64 + (k - 1024)];
        __nv_bfloat16 h = __float2bfloat16(v);
        __nv_bfloat16 lo = __float2bfloat16(v - __bfloat162float(h));
        int kc = k >> 4, fr = nl >> 3;
        int lane = ((nl & 7) << 2) | ((k & 7) >> 1);
        int w = (k >> 3) & 1, hb = k & 1;
        uint32_t off = (uint32_t)((kc * 4 + fr) * 2) * 256 + lane * 8 + w * 4 + hb * 2;
        *reinterpret_cast<__nv_bfloat16*>(smem + off) = h;
        *reinterpret_cast<__nv_bfloat16*>(smem + off + 256) = lo;
    }
    // zero h buffer 0 (h_{-1} = 0)
    {
        uint4 z = make_uint4(0, 0, 0, 0);
        for (int i = bid * 128 + tid; i < HBUF; i += NCTA * 128) hA[i] = z;
    }
    grid_sync();

    const int mtg0 = (m0 >> 4) + wm * 2;   // this warp's first global m16 tile
    const int kcd  = (n0 >> 4) + wn;       // epilogue dest kc (next-step A chunk)

    for (int t = 0; t < T_; ++t) {
        const uint4* __restrict__ hcur = hA + (size_t)(t & 1) * HBUF;
        uint4* __restrict__ hnxt       = hA + (size_t)((t + 1) & 1) * HBUF;
        const uint4* __restrict__ xpt  = xp + (size_t)t * 4096;

        float chh[2][2][4], chl[2][2][4], clh[2][2][4];
#pragma unroll
        for (int a = 0; a < 2; ++a)
#pragma unroll
            for (int b = 0; b < 2; ++b)
#pragma unroll
                for (int j = 0; j < 4; ++j)
                    chh[a][b][j] = chl[a][b][j] = clh[a][b][j] = 0.f;

        // A block pointer for (kc, m-tile mi), lane-adjusted; hi at +0, lo at +32
        auto ablk = [&](int kc, int mi) -> const uint4* {
            return (kc < 64)
                ? hcur + ((size_t)((mtg0 + mi) * 64 + kc) * 2) * 32 + l
                : xpt  + ((size_t)((mtg0 + mi) * 4 + (kc - 64)) * 2) * 32 + l;
        };

        uint4 sAh[3][2], sAl[3][2];
#pragma unroll
        for (int p = 0; p < 3; ++p) {
            const uint4* p0 = ablk(p, 0);
            const uint4* p1 = ablk(p, 1);
            sAh[p][0] = p0[0];  sAl[p][0] = p0[32];
            sAh[p][1] = p1[0];  sAl[p][1] = p1[32];
        }

#pragma unroll
        for (int kc = 0; kc < NKC; ++kc) {
            const int s = kc % 3;
            uint32_t bh0[2], bh1[2], bl0[2], bl1[2];
            uint32_t ba = sB + (uint32_t)kc * 2048 + (uint32_t)(wn * 2) * 512 + l * 8;
            lds64(bh0, ba);        lds64(bl0, ba + 256);
            lds64(bh1, ba + 512);  lds64(bl1, ba + 768);

            const uint32_t* ah0 = reinterpret_cast<const uint32_t*>(&sAh[s][0]);
            const uint32_t* ah1 = reinterpret_cast<const uint32_t*>(&sAh[s][1]);
            const uint32_t* al0 = reinterpret_cast<const uint32_t*>(&sAl[s][0]);
            const uint32_t* al1 = reinterpret_cast<const uint32_t*>(&sAl[s][1]);

            mma16816(chh[0][0], ah0, bh0);  mma16816(chh[0][1], ah0, bh1);
            mma16816(chh[1][0], ah1, bh0);  mma16816(chh[1][1], ah1, bh1);
            mma16816(chl[0][0], ah0, bl0);  mma16816(chl[0][1], ah0, bl1);
            mma16816(chl[1][0], ah1, bl0);  mma16816(chl[1][1], ah1, bl1);
            mma16816(clh[0][0], al0, bh0);  mma16816(clh[0][1], al0, bh1);
            mma16816(clh[1][0], al1, bh0);  mma16816(clh[1][1], al1, bh1);

            if (kc + 3 < NKC) {
                const uint4* p0 = ablk(kc + 3, 0);
                const uint4* p1 = ablk(kc + 3, 1);
                sAh[s][0] = p0[0];  sAl[s][0] = p0[32];
                sAh[s][1] = p1[0];  sAl[s][1] = p1[32];
            }
        }

        // ---- epilogue: relu, bf16 split, store in next-step A-frag layout ----
#pragma unroll
        for (int mi = 0; mi < 2; ++mi) {
            float v[2][4], r[2][4];
#pragma unroll
            for (int f = 0; f < 2; ++f)
#pragma unroll
                for (int j = 0; j < 4; ++j) {
                    float s = chh[mi][f][j] + chl[mi][f][j] + clh[mi][f][j];
                    s = fmaxf(s, 0.f);
                    v[f][j] = s;
                    r[f][j] = s - __bfloat162float(__float2bfloat16(s));
                }
            uint4 hi4, lo4;
            hi4.x = pk(v[0][0], v[0][1]);  hi4.y = pk(v[0][2], v[0][3]);
            hi4.z = pk(v[1][0], v[1][1]);  hi4.w = pk(v[1][2], v[1][3]);
            lo4.x = pk(r[0][0], r[0][1]);  lo4.y = pk(r[0][2], r[0][3]);
            lo4.z = pk(r[1][0], r[1][1]);  lo4.w = pk(r[1][2], r[1][3]);
            uint4* dst = hnxt + ((size_t)((mtg0 + mi) * 64 + kcd) * 2) * 32 + l;
            dst[0]  = hi4;
            dst[32] = lo4;
            if (t == T_ - 1) {
                int r0 = m0 + wm * 32 + mi * 16 + (l >> 2);
                int c0 = n0 + wn * 16 + 2 * (l & 3);
                *(float2*)&hf[(size_t)r0 * H_ + c0]           = make_float2(v[0][0], v[0][1]);
                *(float2*)&hf[(size_t)(r0 + 8) * H_ + c0]     = make_float2(v[0][2], v[0][3]);
                *(float2*)&hf[(size_t)r0 * H_ + c0 + 8]       = make_float2(v[1][0], v[1][1]);
                *(float2*)&hf[(size_t)(r0 + 8) * H_ + c0 + 8] = make_float2(v[1][2], v[1][3]);
            }
        }
        __threadfence();
        grid_sync();
    }

    // ---- final: out[m][o] = sum_k h[m][k] * Wo[o][k]; 2 batch rows per CTA ---
    {
        float* sw = (float*)smem;                 // [128][129] padded
        float* sh = (float*)smem + 128 * 129;     // [2][1024]
        const int m = bid * 2;
        for (int i = tid; i < 2 * H_; i += 128)
            sh[i] = hf[(size_t)(m + (i >> 10)) * H_ + (i & 1023)];
        float a0 = 0.f, a1 = 0.f;
        for (int k0 = 0; k0 < H_; k0 += 128) {
            __syncthreads();
            for (int i = tid; i < 128 * 128; i += 128) {
                int o = i >> 7, kk = i & 127;
                sw[o * 129 + kk] = Wo[(size_t)o * H_ + k0 + kk];
            }
            __syncthreads();
#pragma unroll 8
            for (int kk = 0; kk < 128; ++kk) {
                float w = sw[tid * 129 + kk];
                a0 = fmaf(sh[k0 + kk], w, a0);
                a1 = fmaf(sh[H_ + k0 + kk], w, a1);
            }
        }
        out[(size_t)m * OUT_ + tid]       = a0;
        out[(size_t)(m + 1) * OUT_ + tid] = a1;
    }
}

// ---------------- launch --------------------------------------------------
extern "C" void kernel_launch(void* const* d_in, const int* in_sizes, int n_in,
                              void* d_out, int out_size) {
    (void)in_sizes; (void)n_in; (void)out_size;
    const float* x  = (const float*)d_in[0];
    const float* Wh = (const float*)d_in[1];
    const float* Wx = (const float*)d_in[2];
    const float* Wo = (const float*)d_in[3];
    float* out = (float*)d_out;

    uint4 *phA, *pxp;
    float* phf;
    cudaGetSymbolAddress((void**)&phA, g_hA);
    cudaGetSymbolAddress((void**)&pxp, g_xp);
    cudaGetSymbolAddress((void**)&phf, g_hf);

    pack_x<<<4096, 256>>>(x, pxp);

    cudaFuncSetAttribute(rnn_mma, cudaFuncAttributeMaxDynamicSharedMemorySize, SMEM_BYTES);
    rnn_mma<<<NCTA, 128, SMEM_BYTES>>>(out, Wh, Wx, Wo, pxp, phA, phf);
}

// round 4
// speedup vs baseline: 2.1528x; 1.8465x over previous
#include <cuda_runtime.h>
#include <cuda_bf16.h>
#include <cstdint>

#define B_    256
#define T_    512
#define IN_   64
#define H_    1024
#define OUT_  128
#define NCTA  128
#define NKC   68                      // K chunks of 16: 64 (h) + 4 (x_t)
#define HBUF  (16 * 64 * 2 * 32)      // uint4s per h buffer: [mt][kc][hl][lane]
#define SMEM_BYTES (NKC * 4 * 2 * 256)   // 139264 B: B slice, frag-packed

// ---------------- persistent device scratch ------------------------------
__device__ uint4 g_hA[2 * HBUF];                   // ping-pong h, A-frag packed (2 MB)
__device__ uint4 g_xp[(size_t)T_ * 16 * 4 * 2 * 32]; // x, A-frag packed per t (32 MB)
__device__ float g_hf[B_ * H_];                    // final h, plain fp32
__device__ unsigned g_bar_count;
__device__ volatile unsigned g_bar_gen;

// ---------------- helpers -------------------------------------------------
__device__ __forceinline__ uint32_t smem_u32(const void* p) {
    uint32_t a;
    asm("{ .reg .u64 t; cvta.to.shared.u64 t, %1; cvt.u32.u64 %0, t; }"
        : "=r"(a) : "l"(p));
    return a;
}

__device__ __forceinline__ uint32_t pk(float a, float b) {
    __nv_bfloat162 t = __floats2bfloat162_rn(a, b);
    return *reinterpret_cast<uint32_t*>(&t);
}

__device__ __forceinline__ void lds64(uint32_t* r, uint32_t a) {
    asm("ld.shared.v2.b32 {%0,%1}, [%2];" : "=r"(r[0]), "=r"(r[1]) : "r"(a));
}

__device__ __forceinline__ void mma16816(float* c, const uint32_t* a, const uint32_t* b) {
    asm("mma.sync.aligned.m16n8k16.row.col.f32.bf16.bf16.f32 "
        "{%0,%1,%2,%3}, {%4,%5,%6,%7}, {%8,%9}, {%0,%1,%2,%3};"
        : "+f"(c[0]), "+f"(c[1]), "+f"(c[2]), "+f"(c[3])
        : "r"(a[0]), "r"(a[1]), "r"(a[2]), "r"(a[3]), "r"(b[0]), "r"(b[1]));
}

__device__ __forceinline__ void grid_sync() {
    __syncthreads();
    if (threadIdx.x == 0) {
        __threadfence();
        unsigned gen = g_bar_gen;
        if (atomicAdd(&g_bar_count, 1u) == NCTA - 1u) {
            atomicExch(&g_bar_count, 0u);
            __threadfence();
            g_bar_gen = gen + 1u;
        } else {
            while (g_bar_gen == gen) { }
        }
        __threadfence();
    }
    __syncthreads();
}

// ---------------- pack x into A-fragment layout (one-time) ----------------
__global__ void pack_x(const float* __restrict__ x, uint4* __restrict__ xp) {
    int id = blockIdx.x * (blockDim.x >> 5) + (threadIdx.x >> 5);
    int l  = threadIdx.x & 31;
    if (id >= T_ * 16 * 4) return;
    int t = id >> 6, mt = (id >> 2) & 15, kcx = id & 3;
    int b0 = mt * 16 + (l >> 2), b1 = b0 + 8;
    int i0 = kcx * 16 + 2 * (l & 3);
    const float* x0 = x + ((size_t)b0 * T_ + t) * IN_;
    const float* x1 = x + ((size_t)b1 * T_ + t) * IN_;
    float v00 = x0[i0], v01 = x0[i0 + 1], v02 = x0[i0 + 8], v03 = x0[i0 + 9];
    float v10 = x1[i0], v11 = x1[i0 + 1], v12 = x1[i0 + 8], v13 = x1[i0 + 9];
    uint4 hi4, lo4;
    hi4.x = pk(v00, v01); hi4.y = pk(v10, v11);
    hi4.z = pk(v02, v03); hi4.w = pk(v12, v13);
    float r00 = v00 - __bfloat162float(__float2bfloat16(v00));
    float r01 = v01 - __bfloat162float(__float2bfloat16(v01));
    float r02 = v02 - __bfloat162float(__float2bfloat16(v02));
    float r03 = v03 - __bfloat162float(__float2bfloat16(v03));
    float r10 = v10 - __bfloat162float(__float2bfloat16(v10));
    float r11 = v11 - __bfloat162float(__float2bfloat16(v11));
    float r12 = v12 - __bfloat162float(__float2bfloat16(v12));
    float r13 = v13 - __bfloat162float(__float2bfloat16(v13));
    lo4.x = pk(r00, r01); lo4.y = pk(r10, r11);
    lo4.z = pk(r02, r03); lo4.w = pk(r12, r13);
    size_t base = (size_t)id * 64 + l;
    xp[base] = hi4;
    xp[base + 32] = lo4;
}

// ---------------- persistent mma.sync RNN --------------------------------
// 128 CTAs x 256 threads (8 warps, wm 0-3 x wn 0-1). CTA tile M64 x N32;
// warp tile m16 x n16. A register-prefetch depth 4.
__global__ void __launch_bounds__(256, 1) rnn_mma(
    float* __restrict__ out, const float* __restrict__ Wh,
    const float* __restrict__ Wx, const float* __restrict__ Wo,
    const uint4* __restrict__ xp, uint4* __restrict__ hA,
    float* __restrict__ hf)
{
    extern __shared__ __align__(16) uint8_t smem[];
    const int tid = threadIdx.x, l = tid & 31;
    const int wid = tid >> 5, wm = wid >> 1, wn = wid & 1;
    const int bid = blockIdx.x;
    const int m0 = (bid >> 5) << 6;        // batch tile: 4 x 64
    const int n0 = (bid & 31) << 5;        // hidden tile: 32 x 32
    const uint32_t sB = smem_u32(smem);

    // ---- one-time: pack B slice (rows n0..n0+31 of [Wh | Wx]) into smem ----
    for (int e = tid; e < 32 * 1088; e += 256) {
        int nl = e / 1088, k = e - nl * 1088;
        float v = (k < 1024) ? Wh[(size_t)(n0 + nl) * 1024 + k]
                             : Wx[(size_t)(n0 + nl) * 64 + (k - 1024)];
        __nv_bfloat16 h = __float2bfloat16(v);
        __nv_bfloat16 lo = __float2bfloat16(v - __bfloat162float(h));
        int kc = k >> 4, fr = nl >> 3;
        int lane = ((nl & 7) << 2) | ((k & 7) >> 1);
        int w = (k >> 3) & 1, hb = k & 1;
        uint32_t off = (uint32_t)((kc * 4 + fr) * 2) * 256 + lane * 8 + w * 4 + hb * 2;
        *reinterpret_cast<__nv_bfloat16*>(smem + off) = h;
        *reinterpret_cast<__nv_bfloat16*>(smem + off + 256) = lo;
    }
    // zero h buffer 0 (h_{-1} = 0)
    {
        uint4 z = make_uint4(0, 0, 0, 0);
        for (int i = bid * 256 + tid; i < HBUF; i += NCTA * 256) hA[i] = z;
    }
    grid_sync();

    const int mtg = (m0 >> 4) + wm;        // this warp's global m16 tile (0-15)
    const int kcd = (n0 >> 4) + wn;        // epilogue dest kc (next-step A chunk)

    for (int t = 0; t < T_; ++t) {
        const uint4* __restrict__ hcur = hA + (size_t)(t & 1) * HBUF;
        uint4* __restrict__ hnxt       = hA + (size_t)((t + 1) & 1) * HBUF;
        const uint4* __restrict__ xpt  = xp + (size_t)t * 4096;

        float chh[2][4], chl[2][4], clh[2][4];
#pragma unroll
        for (int f = 0; f < 2; ++f)
#pragma unroll
            for (int j = 0; j < 4; ++j)
                chh[f][j] = chl[f][j] = clh[f][j] = 0.f;

        auto ablk = [&](int kc) -> const uint4* {
            return (kc < 64)
                ? hcur + ((size_t)(mtg * 64 + kc) * 2) * 32 + l
                : xpt  + ((size_t)(mtg * 4 + (kc - 64)) * 2) * 32 + l;
        };

        uint4 sAh[4], sAl[4];
#pragma unroll
        for (int p = 0; p < 4; ++p) {
            const uint4* ap = ablk(p);
            sAh[p] = ap[0];
            sAl[p] = ap[32];
        }

#pragma unroll 4
        for (int kc = 0; kc < NKC; ++kc) {
            const int s = kc & 3;
            uint32_t bh0[2], bh1[2], bl0[2], bl1[2];
            uint32_t ba = sB + (uint32_t)kc * 2048 + (uint32_t)(wn * 2) * 512 + l * 8;
            lds64(bh0, ba);        lds64(bl0, ba + 256);
            lds64(bh1, ba + 512);  lds64(bl1, ba + 768);

            const uint32_t* ah = reinterpret_cast<const uint32_t*>(&sAh[s]);
            const uint32_t* al = reinterpret_cast<const uint32_t*>(&sAl[s]);

            mma16816(chh[0], ah, bh0);  mma16816(chh[1], ah, bh1);
            mma16816(chl[0], ah, bl0);  mma16816(chl[1], ah, bl1);
            mma16816(clh[0], al, bh0);  mma16816(clh[1], al, bh1);

            if (kc + 4 < NKC) {
                const uint4* ap = ablk(kc + 4);
                sAh[s] = ap[0];
                sAl[s] = ap[32];
            }
        }

        // ---- epilogue: relu, bf16 split, store in next-step A-frag layout ----
        {
            float v[2][4], r[2][4];
#pragma unroll
            for (int f = 0; f < 2; ++f)
#pragma unroll
                for (int j = 0; j < 4; ++j) {
                    float s = chh[f][j] + chl[f][j] + clh[f][j];
                    s = fmaxf(s, 0.f);
                    v[f][j] = s;
                    r[f][j] = s - __bfloat162float(__float2bfloat16(s));
                }
            uint4 hi4, lo4;
            hi4.x = pk(v[0][0], v[0][1]);  hi4.y = pk(v[0][2], v[0][3]);
            hi4.z = pk(v[1][0], v[1][1]);  hi4.w = pk(v[1][2], v[1][3]);
            lo4.x = pk(r[0][0], r[0][1]);  lo4.y = pk(r[0][2], r[0][3]);
            lo4.z = pk(r[1][0], r[1][1]);  lo4.w = pk(r[1][2], r[1][3]);
            uint4* dst = hnxt + ((size_t)(mtg * 64 + kcd) * 2) * 32 + l;
            dst[0]  = hi4;
            dst[32] = lo4;
            if (t == T_ - 1) {
                int r0 = mtg * 16 + (l >> 2);
                int c0 = n0 + wn * 16 + 2 * (l & 3);
                *(float2*)&hf[(size_t)r0 * H_ + c0]           = make_float2(v[0][0], v[0][1]);
                *(float2*)&hf[(size_t)(r0 + 8) * H_ + c0]     = make_float2(v[0][2], v[0][3]);
                *(float2*)&hf[(size_t)r0 * H_ + c0 + 8]       = make_float2(v[1][0], v[1][1]);
                *(float2*)&hf[(size_t)(r0 + 8) * H_ + c0 + 8] = make_float2(v[1][2], v[1][3]);
            }
        }
        grid_sync();
    }

    // ---- final: out[m][o] = sum_k h[m][k] * Wo[o][k]; 2 batch rows per CTA ---
    {
        float* sw = (float*)smem;                 // [128][129] padded
        float* sh = (float*)smem + 128 * 129;     // [2][1024]
        const int m = bid * 2;
        const int half = tid >> 7, o = tid & 127;
        for (int i = tid; i < 2 * H_; i += 256)
            sh[i] = hf[(size_t)(m + (i >> 10)) * H_ + (i & 1023)];
        float acc = 0.f;
        for (int k0 = 0; k0 < H_; k0 += 128) {
            __syncthreads();
            for (int i = tid; i < 128 * 128; i += 256) {
                int oo = i >> 7, kk = i & 127;
                sw[oo * 129 + kk] = Wo[(size_t)oo * H_ + k0 + kk];
            }
            __syncthreads();
#pragma unroll 8
            for (int kk = 0; kk < 128; ++kk)
                acc = fmaf(sh[half * H_ + k0 + kk], sw[o * 129 + kk], acc);
        }
        out[(size_t)(m + half) * OUT_ + o] = acc;
    }
}

// ---------------- launch --------------------------------------------------
extern "C" void kernel_launch(void* const* d_in, const int* in_sizes, int n_in,
                              void* d_out, int out_size) {
    (void)in_sizes; (void)n_in; (void)out_size;
    const float* x  = (const float*)d_in[0];
    const float* Wh = (const float*)d_in[1];
    const float* Wx = (const float*)d_in[2];
    const float* Wo = (const float*)d_in[3];
    float* out = (float*)d_out;

    uint4 *phA, *pxp;
    float* phf;
    cudaGetSymbolAddress((void**)&phA, g_hA);
    cudaGetSymbolAddress((void**)&pxp, g_xp);
    cudaGetSymbolAddress((void**)&phf, g_hf);

    pack_x<<<4096, 256>>>(x, pxp);

    cudaFuncSetAttribute(rnn_mma, cudaFuncAttributeMaxDynamicSharedMemorySize, SMEM_BYTES);
    rnn_mma<<<NCTA, 256, SMEM_BYTES>>>(out, Wh, Wx, Wo, pxp, phA, phf);
}